// round 8
// baseline (speedup 1.0000x reference)
#include <cuda_runtime.h>
#include <math_constants.h>

#define BATCH 256
#define SEQ   2048
#define IDIM  32
#define HDIM  128

// Scratch (allocation-free rule: static __device__ array)
__device__ float g_hid[(size_t)SEQ * BATCH * HDIM];     // [S][B][H]

// Cheap accurate tanh: abs err ~1e-7, correct saturation at +-inf
__device__ __forceinline__ float tanh_fast(float x) {
    float e = __expf(2.0f * x);
    return 1.0f - 2.0f / (e + 1.0f);
}

// ---------------------------------------------------------------------------
// Kernel B: fused input-projection + sequential recurrence.
// ONE batch per 128-thread CTA, grid=BATCH, 2 CTAs/SM (independent barrier
// domains). Thread j owns hidden unit j: Wh column in 128 regs, Wi column in
// 32 regs. Per step:
//   hn[j] = (sum_i x[t][i]*Wi[i][j]) + bi[j] + bh[j] + (sum_k h0[k]*Wh[k][j])
// x rows (128B) are register-prefetched 4 steps ahead (lane i holds x[t][i],
// replicated per warp) and broadcast via 32 in-warp shuffles — no smem ring,
// no extra barriers, no g_xproj DRAM round-trip.
// h0 double-buffered in smem; one barrier per step.
// ---------------------------------------------------------------------------
__global__ __launch_bounds__(128, 2) void rnn_kernel(const float* __restrict__ x,
                                                     const float* __restrict__ Wi,
                                                     const float* __restrict__ bi,
                                                     const float* __restrict__ Wh,
                                                     const float* __restrict__ bh,
                                                     const int* __restrict__ rdp) {
    const int j    = threadIdx.x;          // 0..127
    const int lane = j & 31;
    const int b    = blockIdx.x;
    const int rd   = *rdp;

    __shared__ __align__(16) float hbuf[2][HDIM];  // [parity][j]
    hbuf[0][j] = 0.f;
    hbuf[1][j] = 0.f;

    float w[HDIM];
#pragma unroll
    for (int k = 0; k < HDIM; k++) w[k] = Wh[k * HDIM + j];
    float wi[IDIM];
#pragma unroll
    for (int i = 0; i < IDIM; i++) wi[i] = Wi[i * HDIM + j];
    const float bsum = bi[j] + bh[j];

    const float* xrow = x + (size_t)b * SEQ * IDIM;     // 32-float rows
    float*       hout = g_hid + (size_t)b * HDIM + j;   // + t*BATCH*HDIM per step

    float hstart = 0.f, ht = 0.f, h0self = 0.f;
    int c = 0;                                          // t % rd tracker

    // prime the depth-4 x prefetch ring (lane i holds x[b][t][i], per warp)
    float x0 = __ldg(xrow + 0 * IDIM + lane);
    float x1 = __ldg(xrow + 1 * IDIM + lane);
    float x2 = __ldg(xrow + 2 * IDIM + lane);
    float x3 = __ldg(xrow + 3 * IDIM + lane);
    __syncthreads();

#define RNN_STEP(T, XV)                                                       \
    {                                                                         \
        const int t = (T);                                                    \
        /* x contribution: broadcast the prefetched row across the warp */    \
        float xa = bsum;                                                      \
        _Pragma("unroll")                                                     \
        for (int i = 0; i < IDIM; i++)                                        \
            xa = fmaf(__shfl_sync(0xffffffffu, XV, i), wi[i], xa);            \
        if (t + 4 < SEQ) XV = __ldg(xrow + (size_t)(t + 4) * IDIM + lane);    \
        /* recurrent contribution */                                          \
        const float* hrow = &hbuf[t & 1][0];                                  \
        float a0 = 0.f, a1 = 0.f, a2 = 0.f, a3 = 0.f;                         \
        _Pragma("unroll")                                                     \
        for (int k = 0; k < HDIM; k += 4) {                                   \
            const float4 h4 = *(const float4*)(hrow + k);                     \
            a0 = fmaf(h4.x, w[k + 0], a0);                                    \
            a1 = fmaf(h4.y, w[k + 1], a1);                                    \
            a2 = fmaf(h4.z, w[k + 2], a2);                                    \
            a3 = fmaf(h4.w, w[k + 3], a3);                                    \
        }                                                                     \
        const float hn = ((a0 + a1) + (a2 + a3)) + xa;                        \
        const bool g0 = (t == 0);                                             \
        const bool g1 = (t == SEQ - 2);                                       \
        const bool g4 = (rd == 1) && !g0 && !g1;                              \
        const bool g2 = (!g0 && !g1 && !g4 && (c == 0));                      \
        const float add  = g1 ? hstart : (g4 ? h0self : (g2 ? ht : 0.f));     \
        const float cand = tanh_fast(hn + add);                               \
        const float h0n  = g0 ? h0self : cand;                                \
        if (g0) hstart = hn;                                                  \
        if (g2) ht = hn;                                                      \
        h0self = h0n;                                                         \
        hout[(size_t)t * (BATCH * HDIM)] = hn;                                \
        hbuf[(t + 1) & 1][j] = h0n;                                           \
        if (++c == rd) c = 0;                                                 \
        __syncthreads();                                                      \
    }

    for (int t0 = 0; t0 < SEQ; t0 += 4) {
        RNN_STEP(t0 + 0, x0);
        RNN_STEP(t0 + 1, x1);
        RNN_STEP(t0 + 2, x2);
        RNN_STEP(t0 + 3, x3);
    }
#undef RNN_STEP
}

// ---------------------------------------------------------------------------
// Kernel C: fully fused attention + output. One CTA per output row r
// (reshape-group: t in [8r,8r+8), all b; warp = dt). Single pass over g_hid:
// pass 1 computes score p AND q = h . Wd_row(m) together; then softmax-sum
// and weighted-sum fuse into one strided loop (out = sum(e*q)/sum(e) + bd).
// ---------------------------------------------------------------------------
__global__ __launch_bounds__(256) void out_kernel(const float* __restrict__ Wa,
                                                  const float* __restrict__ ba,
                                                  const float* __restrict__ Wd,
                                                  const float* __restrict__ bd,
                                                  float* __restrict__ out) {
    const int r    = blockIdx.x;
    const int warp = threadIdx.x >> 5;     // dt 0..7
    const int lane = threadIdx.x & 31;

    __shared__ float sc[8 * BATCH];        // scores (group-local m = dt*256+b)
    __shared__ float qv[8 * BATCH];        // q[m] = hid_row(m) . Wd_row(m)
    __shared__ float red1[8], red2[8];

    const float4 wa4 = ((const float4*)Wa)[lane];
    const int t = r * 8 + warp;
    const float* hbase = g_hid + (size_t)t * BATCH * HDIM;
    const float* wdb   = Wd + (size_t)(warp * BATCH) * HDIM;
    const float  ba0   = ba[0];

    // pass 1: score + Wd-dot in the same read of g_hid
    for (int b = 0; b < BATCH; b++) {
        const float4 h4 = ((const float4*)(hbase + (size_t)b * HDIM))[lane];
        const float4 d4 = ((const float4*)(wdb + (size_t)b * HDIM))[lane];
        float p = h4.x * wa4.x + h4.y * wa4.y + h4.z * wa4.z + h4.w * wa4.w;
        float q = h4.x * d4.x + h4.y * d4.y + h4.z * d4.z + h4.w * d4.w;
#pragma unroll
        for (int o = 16; o > 0; o >>= 1) {
            p += __shfl_xor_sync(0xffffffffu, p, o);
            q += __shfl_xor_sync(0xffffffffu, q, o);
        }
        if (lane == 0) { sc[warp * BATCH + b] = p + ba0; qv[warp * BATCH + b] = q; }
    }
    __syncthreads();

    // block max of scores
    float mx = -CUDART_INF_F;
    for (int i = threadIdx.x; i < 8 * BATCH; i += 256) mx = fmaxf(mx, sc[i]);
#pragma unroll
    for (int o = 16; o > 0; o >>= 1) mx = fmaxf(mx, __shfl_xor_sync(0xffffffffu, mx, o));
    if (lane == 0) red1[warp] = mx;
    __syncthreads();
    mx = red1[0];
#pragma unroll
    for (int i = 1; i < 8; i++) mx = fmaxf(mx, red1[i]);
    __syncthreads();

    // fused exp-sum + weighted accumulation
    float sm = 0.f, wacc = 0.f;
    for (int i = threadIdx.x; i < 8 * BATCH; i += 256) {
        const float e = __expf(sc[i] - mx);
        sm += e;
        wacc = fmaf(e, qv[i], wacc);
    }
#pragma unroll
    for (int o = 16; o > 0; o >>= 1) {
        sm   += __shfl_xor_sync(0xffffffffu, sm, o);
        wacc += __shfl_xor_sync(0xffffffffu, wacc, o);
    }
    if (lane == 0) { red1[warp] = sm; red2[warp] = wacc; }
    __syncthreads();
    if (threadIdx.x == 0) {
        float s = 0.f, v = 0.f;
#pragma unroll
        for (int i = 0; i < 8; i++) { s += red1[i]; v += red2[i]; }
        out[r] = v / s + bd[0];
    }
}

// ---------------------------------------------------------------------------
extern "C" void kernel_launch(void* const* d_in, const int* in_sizes, int n_in,
                              void* d_out, int out_size) {
    const float* x  = (const float*)d_in[0];
    const float* Wi = (const float*)d_in[1];
    const float* bi = (const float*)d_in[2];
    const float* Wh = (const float*)d_in[3];
    const float* bh = (const float*)d_in[4];
    const float* Wa = (const float*)d_in[5];
    const float* ba = (const float*)d_in[6];
    const float* Wd = (const float*)d_in[7];
    const float* bd = (const float*)d_in[8];
    const int*   rd = (const int*)d_in[9];
    float* out = (float*)d_out;

    rnn_kernel<<<BATCH, 128>>>(x, Wi, bi, Wh, bh, rd);
    out_kernel<<<BATCH, 256>>>(Wa, ba, Wd, bd, out);
}

// round 9
// speedup vs baseline: 1.1707x; 1.1707x over previous
#include <cuda_runtime.h>
#include <math_constants.h>

#define BATCH 256
#define SEQ   2048
#define IDIM  32
#define HDIM  128
#define TSA   64   // timesteps per CTA in the projection kernel

// Scratch (allocation-free rule: static __device__ arrays)
__device__ float g_xproj[(size_t)BATCH * SEQ * HDIM];   // [B][S][H], includes bi+bh
__device__ float g_hid[(size_t)SEQ * BATCH * HDIM];     // [S][B][H]

// Cheap accurate tanh: abs err ~1e-7, correct saturation at +-inf
__device__ __forceinline__ float tanh_fast(float x) {
    float e = __expf(2.0f * x);
    return 1.0f - 2.0f / (e + 1.0f);
}

// ---------------------------------------------------------------------------
// Kernel A: xproj[b][t][j] = sum_i x[b][t][i]*Wi[i][j] + bi[j] + bh[j]
// ---------------------------------------------------------------------------
__global__ __launch_bounds__(128) void xproj_kernel(const float* __restrict__ x,
                                                    const float* __restrict__ Wi,
                                                    const float* __restrict__ bi,
                                                    const float* __restrict__ bh) {
    const int b  = blockIdx.x;
    const int t0 = blockIdx.y * TSA;
    const int j  = threadIdx.x;            // 0..127

    __shared__ __align__(16) float xs[TSA][IDIM];

    float w[IDIM];
#pragma unroll
    for (int i = 0; i < IDIM; i++) w[i] = Wi[i * HDIM + j];
    const float bsum = bi[j] + bh[j];

    const float4* xin4 = (const float4*)(x + ((size_t)b * SEQ + t0) * IDIM);
    float4* xs4 = (float4*)&xs[0][0];
    for (int idx = threadIdx.x; idx < TSA * IDIM / 4; idx += blockDim.x)
        xs4[idx] = xin4[idx];
    __syncthreads();

    float* outp = g_xproj + ((size_t)b * SEQ + t0) * HDIM + j;
#pragma unroll 2
    for (int ts = 0; ts < TSA; ts++) {
        float a0 = bsum, a1 = 0.f, a2 = 0.f, a3 = 0.f;
#pragma unroll
        for (int i = 0; i < IDIM; i += 4) {
            a0 = fmaf(xs[ts][i + 0], w[i + 0], a0);
            a1 = fmaf(xs[ts][i + 1], w[i + 1], a1);
            a2 = fmaf(xs[ts][i + 2], w[i + 2], a2);
            a3 = fmaf(xs[ts][i + 3], w[i + 3], a3);
        }
        outp[(size_t)ts * HDIM] = (a0 + a1) + (a2 + a3);
    }
}

// ---------------------------------------------------------------------------
// Kernel B: sequential recurrence (R7-proven config). ONE batch per
// 128-thread CTA, grid=BATCH, 2 CTAs/SM. Thread j owns unit j; Wh column in
// 128 regs; h0 double-buffered in smem; one barrier/step; depth-4 register
// prefetch ring on the g_xproj stream.
// ---------------------------------------------------------------------------
__global__ __launch_bounds__(128, 2) void rnn_kernel(const float* __restrict__ Wh,
                                                     const int* __restrict__ rdp) {
    const int j = threadIdx.x;             // 0..127
    const int b = blockIdx.x;
    const int rd = *rdp;

    __shared__ __align__(16) float hbuf[2][HDIM];  // [parity][j]
    hbuf[0][j] = 0.f;
    hbuf[1][j] = 0.f;

    float w[HDIM];
#pragma unroll
    for (int k = 0; k < HDIM; k++) w[k] = Wh[k * HDIM + j];

    const float* xp   = g_xproj + (size_t)b * SEQ * HDIM + j;
    float*       hout = g_hid + (size_t)b * HDIM + j;   // + t*BATCH*HDIM per step

    float hstart = 0.f, ht = 0.f, h0self = 0.f;
    int c = 0;                                          // t % rd tracker

    float x0 = __ldg(xp + 0 * HDIM);
    float x1 = __ldg(xp + 1 * HDIM);
    float x2 = __ldg(xp + 2 * HDIM);
    float x3 = __ldg(xp + 3 * HDIM);
    __syncthreads();

#define RNN_STEP(T, XV)                                                       \
    {                                                                         \
        const int t = (T);                                                    \
        const float xcur = XV;                                                \
        if (t + 4 < SEQ) XV = __ldg(xp + (size_t)(t + 4) * HDIM);             \
        const float* hrow = &hbuf[t & 1][0];                                  \
        float a0 = 0.f, a1 = 0.f, a2 = 0.f, a3 = 0.f;                         \
        _Pragma("unroll")                                                     \
        for (int k = 0; k < HDIM; k += 4) {                                   \
            const float4 h4 = *(const float4*)(hrow + k);                     \
            a0 = fmaf(h4.x, w[k + 0], a0);                                    \
            a1 = fmaf(h4.y, w[k + 1], a1);                                    \
            a2 = fmaf(h4.z, w[k + 2], a2);                                    \
            a3 = fmaf(h4.w, w[k + 3], a3);                                    \
        }                                                                     \
        const float hn = ((a0 + a1) + (a2 + a3)) + xcur;                      \
        const bool g0 = (t == 0);                                             \
        const bool g1 = (t == SEQ - 2);                                       \
        const bool g4 = (rd == 1) && !g0 && !g1;                              \
        const bool g2 = (!g0 && !g1 && !g4 && (c == 0));                      \
        const float add  = g1 ? hstart : (g4 ? h0self : (g2 ? ht : 0.f));     \
        const float cand = tanh_fast(hn + add);                               \
        const float h0n  = g0 ? h0self : cand;                                \
        if (g0) hstart = hn;                                                  \
        if (g2) ht = hn;                                                      \
        h0self = h0n;                                                         \
        hout[(size_t)t * (BATCH * HDIM)] = hn;                                \
        hbuf[(t + 1) & 1][j] = h0n;                                           \
        if (++c == rd) c = 0;                                                 \
        __syncthreads();                                                      \
    }

    for (int t0 = 0; t0 < SEQ; t0 += 4) {
        RNN_STEP(t0 + 0, x0);
        RNN_STEP(t0 + 1, x1);
        RNN_STEP(t0 + 2, x2);
        RNN_STEP(t0 + 3, x3);
    }
#undef RNN_STEP
}

// ---------------------------------------------------------------------------
// Kernel C: fused attention + output, 1024 threads (32 warps) per CTA.
// One CTA per output row r (reshape-group: t in [8r,8r+8), all b).
// Warp w covers dt = w>>2 and batch-quarter (w&3)*64..+64: 4x the warp
// parallelism of the 256-thread version (was occ=21%, issue=12.8%).
// Single pass over g_hid: p = h.Wa and q = h.Wd_row(m) in one read; then
// block softmax-max, fused exp-sum + weighted-sum; out = sum(e*q)/sum(e)+bd.
// ---------------------------------------------------------------------------
__global__ __launch_bounds__(1024) void out_kernel(const float* __restrict__ Wa,
                                                   const float* __restrict__ ba,
                                                   const float* __restrict__ Wd,
                                                   const float* __restrict__ bd,
                                                   float* __restrict__ out) {
    const int r    = blockIdx.x;
    const int w    = threadIdx.x >> 5;     // 0..31
    const int lane = threadIdx.x & 31;
    const int dt   = w >> 2;               // 0..7
    const int b0   = (w & 3) * 64;         // batch-quarter start

    __shared__ float sc[8 * BATCH];        // scores (group-local m = dt*256+b)
    __shared__ float qv[8 * BATCH];        // q[m] = hid_row(m) . Wd_row(m)
    __shared__ float red1[32], red2[32];

    const float4 wa4 = ((const float4*)Wa)[lane];
    const int t = r * 8 + dt;
    const float* hbase = g_hid + (size_t)t * BATCH * HDIM;
    const float* wdb   = Wd + (size_t)(dt * BATCH) * HDIM;
    const float  ba0   = ba[0];

    // pass 1: score + Wd-dot in the same read of g_hid (64 b per warp)
    for (int bb = 0; bb < 64; bb++) {
        const int b = b0 + bb;
        const float4 h4 = ((const float4*)(hbase + (size_t)b * HDIM))[lane];
        const float4 d4 = ((const float4*)(wdb + (size_t)b * HDIM))[lane];
        float p = h4.x * wa4.x + h4.y * wa4.y + h4.z * wa4.z + h4.w * wa4.w;
        float q = h4.x * d4.x + h4.y * d4.y + h4.z * d4.z + h4.w * d4.w;
#pragma unroll
        for (int o = 16; o > 0; o >>= 1) {
            p += __shfl_xor_sync(0xffffffffu, p, o);
            q += __shfl_xor_sync(0xffffffffu, q, o);
        }
        if (lane == 0) { sc[dt * BATCH + b] = p + ba0; qv[dt * BATCH + b] = q; }
    }
    __syncthreads();

    // block max of scores (2 elems/thread)
    float mx = fmaxf(sc[threadIdx.x], sc[threadIdx.x + 1024]);
#pragma unroll
    for (int o = 16; o > 0; o >>= 1) mx = fmaxf(mx, __shfl_xor_sync(0xffffffffu, mx, o));
    if (lane == 0) red1[w] = mx;
    __syncthreads();
    mx = red1[0];
#pragma unroll
    for (int i = 1; i < 32; i++) mx = fmaxf(mx, red1[i]);
    __syncthreads();

    // fused exp-sum + weighted accumulation (2 elems/thread)
    float sm = 0.f, wacc = 0.f;
#pragma unroll
    for (int rep = 0; rep < 2; rep++) {
        const int i = threadIdx.x + rep * 1024;
        const float e = __expf(sc[i] - mx);
        sm += e;
        wacc = fmaf(e, qv[i], wacc);
    }
#pragma unroll
    for (int o = 16; o > 0; o >>= 1) {
        sm   += __shfl_xor_sync(0xffffffffu, sm, o);
        wacc += __shfl_xor_sync(0xffffffffu, wacc, o);
    }
    if (lane == 0) { red1[w] = sm; red2[w] = wacc; }
    __syncthreads();
    if (threadIdx.x == 0) {
        float s = 0.f, v = 0.f;
#pragma unroll
        for (int i = 0; i < 32; i++) { s += red1[i]; v += red2[i]; }
        out[r] = v / s + bd[0];
    }
}

// ---------------------------------------------------------------------------
extern "C" void kernel_launch(void* const* d_in, const int* in_sizes, int n_in,
                              void* d_out, int out_size) {
    const float* x  = (const float*)d_in[0];
    const float* Wi = (const float*)d_in[1];
    const float* bi = (const float*)d_in[2];
    const float* Wh = (const float*)d_in[3];
    const float* bh = (const float*)d_in[4];
    const float* Wa = (const float*)d_in[5];
    const float* ba = (const float*)d_in[6];
    const float* Wd = (const float*)d_in[7];
    const float* bd = (const float*)d_in[8];
    const int*   rd = (const int*)d_in[9];
    float* out = (float*)d_out;

    dim3 gA(BATCH, SEQ / TSA);
    xproj_kernel<<<gA, 128>>>(x, Wi, bi, bh);
    rnn_kernel<<<BATCH, 128>>>(Wh, rd);
    out_kernel<<<BATCH, 1024>>>(Wa, ba, Wd, bd, out);
}